// round 1
// baseline (speedup 1.0000x reference)
#include <cuda_runtime.h>
#include <math.h>

// Problem constants: B=4, L=2048, D=1024, H=16, Dh=64, 3D=3072
#define BATCH   4
#define SEQ     2048
#define EMBD    1024
#define NHEAD   16
#define HDIM    64
#define TOKENS  (BATCH * SEQ)            // 8192
#define QKVDIM  (3 * EMBD)               // 3072

// ---------------- scratch (static __device__, no allocation) ----------------
__device__ float g_qkv[(size_t)TOKENS * QKVDIM];          // 8192 x 3072
__device__ float g_q[(size_t)BATCH * NHEAD * SEQ * HDIM]; // [B,H,L,Dh]
__device__ float g_k[(size_t)BATCH * NHEAD * SEQ * HDIM];
__device__ float g_v[(size_t)BATCH * NHEAD * SEQ * HDIM];
__device__ float g_att[(size_t)TOKENS * EMBD];            // [B,L,D]

// ---------------- generic tiled fp32 GEMM: C = A @ B + bias -----------------
// BM=BN=64, BK=16, 256 threads, 4x4 microtile per thread.
__global__ __launch_bounds__(256) void gemm_bias_kernel(
    const float* __restrict__ A, const float* __restrict__ B,
    const float* __restrict__ bias, float* __restrict__ C,
    int M, int N, int K) {
  __shared__ float As[16][64];  // transposed: As[k][m]
  __shared__ float Bs[16][64];  // Bs[k][n]
  const int tid = threadIdx.x;
  const int tx = tid & 15, ty = tid >> 4;
  const int m0 = blockIdx.y << 6, n0 = blockIdx.x << 6;
  const int arow = tid >> 2, acol = (tid & 3) << 2;
  const int brow = tid >> 4, bcol = (tid & 15) << 2;
  float acc[4][4] = {};
  for (int k0 = 0; k0 < K; k0 += 16) {
    float4 av = *(const float4*)(A + (size_t)(m0 + arow) * K + k0 + acol);
    As[acol + 0][arow] = av.x;
    As[acol + 1][arow] = av.y;
    As[acol + 2][arow] = av.z;
    As[acol + 3][arow] = av.w;
    *(float4*)(&Bs[brow][bcol]) =
        *(const float4*)(B + (size_t)(k0 + brow) * N + n0 + bcol);
    __syncthreads();
#pragma unroll
    for (int kk = 0; kk < 16; kk++) {
      float4 a4 = *(const float4*)(&As[kk][ty << 2]);
      float4 b4 = *(const float4*)(&Bs[kk][tx << 2]);
      float ar[4] = {a4.x, a4.y, a4.z, a4.w};
      float br[4] = {b4.x, b4.y, b4.z, b4.w};
#pragma unroll
      for (int i = 0; i < 4; i++)
#pragma unroll
        for (int j = 0; j < 4; j++) acc[i][j] += ar[i] * br[j];
    }
    __syncthreads();
  }
  float4 bi = *(const float4*)(bias + n0 + (tx << 2));
  float bb[4] = {bi.x, bi.y, bi.z, bi.w};
#pragma unroll
  for (int i = 0; i < 4; i++) {
    float4 o;
    o.x = acc[i][0] + bb[0];
    o.y = acc[i][1] + bb[1];
    o.z = acc[i][2] + bb[2];
    o.w = acc[i][3] + bb[3];
    *(float4*)(C + (size_t)(m0 + (ty << 2) + i) * N + n0 + (tx << 2)) = o;
  }
}

// ---------------- RoPE + split/transpose to [B,H,L,Dh] ----------------------
__global__ __launch_bounds__(256) void rope_split_kernel(
    const float* __restrict__ qkv, float* __restrict__ Q,
    float* __restrict__ K, float* __restrict__ V) {
  const int token = blockIdx.x;          // 0..8191
  const int b = token >> 11;             // /2048
  const int l = token & 2047;
  const float* row = qkv + (size_t)token * QKVDIM;
  // q and k: 16 heads * 32 pairs = 512 pairs
  for (int idx = threadIdx.x; idx < 512; idx += 256) {
    const int h = idx >> 5;
    const int i = idx & 31;
    const float inv_freq = 1.0f / powf(10000.0f, (2.0f * (float)i) / 64.0f);
    const float ang = (float)l * inv_freq;
    float s, c;
    sincosf(ang, &s, &c);
    const size_t o = ((size_t)(b * NHEAD + h) * SEQ + l) * HDIM + 2 * i;
    const float q1 = row[h * HDIM + 2 * i];
    const float q2 = row[h * HDIM + 2 * i + 1];
    Q[o]     = q1 * c - q2 * s;
    Q[o + 1] = q1 * s + q2 * c;
    const float k1 = row[EMBD + h * HDIM + 2 * i];
    const float k2 = row[EMBD + h * HDIM + 2 * i + 1];
    K[o]     = k1 * c - k2 * s;
    K[o + 1] = k1 * s + k2 * c;
  }
  // v: plain copy/transpose, 256 float4
  {
    const int idx = threadIdx.x;  // 0..255
    const int h = idx >> 4;
    const int d4 = (idx & 15) << 2;
    float4 vv = *(const float4*)(row + 2 * EMBD + h * HDIM + d4);
    *(float4*)(V + ((size_t)(b * NHEAD + h) * SEQ + l) * HDIM + d4) = vv;
  }
}

// ---------------- causal flash attention (fp32, online softmax) -------------
// Block: one (b, h, 64-row q tile). 256 threads, 4x4 microtiles over 64x64.
#define FLASH_SMEM ((4 * 64 * 65 + 3 * 64) * 4 + 64 * 4)

__global__ __launch_bounds__(256) void flash_kernel(
    const float* __restrict__ Q, const float* __restrict__ K,
    const float* __restrict__ V, const int* __restrict__ amask,
    float* __restrict__ O) {
  extern __shared__ float sm[];
  float* Qs = sm;                 // [64][65]
  float* Ks = Qs + 64 * 65;       // [64][65]
  float* Vs = Ks + 64 * 65;       // [64][65]
  float* Ss = Vs + 64 * 65;       // [64][65]
  float* mrow = Ss + 64 * 65;     // [64]
  float* lrow = mrow + 64;        // [64]
  float* crow = lrow + 64;        // [64]
  int*   msk  = (int*)(crow + 64);// [64]

  const int tid = threadIdx.x;
  const int tx = tid & 15, ty = tid >> 4;
  const int qt = blockIdx.x, h = blockIdx.y, b = blockIdx.z;
  const int q0 = qt << 6;
  const size_t base = (size_t)(b * NHEAD + h) * SEQ * HDIM;

  // load Q tile
#pragma unroll
  for (int i = 0; i < 4; i++) {
    const int r = (tid >> 4) + i * 16;
    const int c = (tid & 15) << 2;
    float4 v = *(const float4*)(Q + base + (size_t)(q0 + r) * HDIM + c);
    Qs[r * 65 + c]     = v.x;
    Qs[r * 65 + c + 1] = v.y;
    Qs[r * 65 + c + 2] = v.z;
    Qs[r * 65 + c + 3] = v.w;
  }
  if (tid < 64) { mrow[tid] = -1e30f; lrow[tid] = 0.0f; }
  float acc[4][4] = {};
  __syncthreads();

  for (int kt = 0; kt <= qt; kt++) {
    const int k0 = kt << 6;
    // load K, V tiles + key mask
#pragma unroll
    for (int i = 0; i < 4; i++) {
      const int r = (tid >> 4) + i * 16;
      const int c = (tid & 15) << 2;
      float4 kv = *(const float4*)(K + base + (size_t)(k0 + r) * HDIM + c);
      Ks[r * 65 + c]     = kv.x;
      Ks[r * 65 + c + 1] = kv.y;
      Ks[r * 65 + c + 2] = kv.z;
      Ks[r * 65 + c + 3] = kv.w;
      float4 vv = *(const float4*)(V + base + (size_t)(k0 + r) * HDIM + c);
      Vs[r * 65 + c]     = vv.x;
      Vs[r * 65 + c + 1] = vv.y;
      Vs[r * 65 + c + 2] = vv.z;
      Vs[r * 65 + c + 3] = vv.w;
    }
    if (tid < 64) msk[tid] = amask[b * SEQ + k0 + tid];
    __syncthreads();

    // S = scale * Q K^T with causal + key mask
    {
      float s[4][4] = {};
      for (int d = 0; d < 64; d++) {
        float qr[4], kr[4];
#pragma unroll
        for (int i = 0; i < 4; i++) qr[i] = Qs[((ty << 2) + i) * 65 + d];
#pragma unroll
        for (int j = 0; j < 4; j++) kr[j] = Ks[((tx << 2) + j) * 65 + d];
#pragma unroll
        for (int i = 0; i < 4; i++)
#pragma unroll
          for (int j = 0; j < 4; j++) s[i][j] += qr[i] * kr[j];
      }
      const bool diag = (kt == qt);
#pragma unroll
      for (int i = 0; i < 4; i++) {
        const int r = (ty << 2) + i;
#pragma unroll
        for (int j = 0; j < 4; j++) {
          const int c = (tx << 2) + j;
          const bool ok = (msk[c] != 0) && (!diag || (c <= r));
          Ss[r * 65 + c] = ok ? s[i][j] * 0.125f : -1e30f;
        }
      }
    }
    __syncthreads();

    // online softmax update (4 lanes per row)
    {
      const int r = tid >> 2, p = tid & 3;
      const int cbase = p << 4;
      float mloc = -1e30f;
#pragma unroll
      for (int t = 0; t < 16; t++) mloc = fmaxf(mloc, Ss[r * 65 + cbase + t]);
      mloc = fmaxf(mloc, __shfl_xor_sync(0xffffffffu, mloc, 1));
      mloc = fmaxf(mloc, __shfl_xor_sync(0xffffffffu, mloc, 2));
      const float mold = mrow[r];
      const float mnew = fmaxf(mold, mloc);
      float sloc = 0.0f;
#pragma unroll
      for (int t = 0; t < 16; t++) {
        const float e = __expf(Ss[r * 65 + cbase + t] - mnew);
        Ss[r * 65 + cbase + t] = e;
        sloc += e;
      }
      sloc += __shfl_xor_sync(0xffffffffu, sloc, 1);
      sloc += __shfl_xor_sync(0xffffffffu, sloc, 2);
      if (p == 0) {
        const float corr = __expf(mold - mnew);
        mrow[r] = mnew;
        lrow[r] = lrow[r] * corr + sloc;
        crow[r] = corr;
      }
    }
    __syncthreads();

    // rescale accumulator, then O += P @ V
    {
      float cr[4];
#pragma unroll
      for (int i = 0; i < 4; i++) cr[i] = crow[(ty << 2) + i];
#pragma unroll
      for (int i = 0; i < 4; i++)
#pragma unroll
        for (int j = 0; j < 4; j++) acc[i][j] *= cr[i];
      for (int kk = 0; kk < 64; kk++) {
        float pr[4], vr[4];
#pragma unroll
        for (int i = 0; i < 4; i++) pr[i] = Ss[((ty << 2) + i) * 65 + kk];
#pragma unroll
        for (int j = 0; j < 4; j++) vr[j] = Vs[kk * 65 + (tx << 2) + j];
#pragma unroll
        for (int i = 0; i < 4; i++)
#pragma unroll
          for (int j = 0; j < 4; j++) acc[i][j] += pr[i] * vr[j];
      }
    }
    __syncthreads();
  }

  // write out in [B, L, H*Dh] layout (ready for proj GEMM)
#pragma unroll
  for (int i = 0; i < 4; i++) {
    const int r = (ty << 2) + i;
    const float inv = 1.0f / lrow[r];
    float4 o;
    o.x = acc[i][0] * inv;
    o.y = acc[i][1] * inv;
    o.z = acc[i][2] * inv;
    o.w = acc[i][3] * inv;
    *(float4*)(O + ((size_t)(b * SEQ + q0 + r)) * EMBD + h * HDIM + (tx << 2)) = o;
  }
}

// ---------------------------------------------------------------------------
extern "C" void kernel_launch(void* const* d_in, const int* in_sizes, int n_in,
                              void* d_out, int out_size) {
  const float* x     = (const float*)d_in[0];
  const float* Wqkv  = (const float*)d_in[1];
  const float* bqkv  = (const float*)d_in[2];
  const float* Wproj = (const float*)d_in[3];
  const float* bproj = (const float*)d_in[4];
  const int*   amask = (const int*)d_in[5];
  float* out = (float*)d_out;

  float *qkv, *q, *k, *v, *att;
  cudaGetSymbolAddress((void**)&qkv, g_qkv);
  cudaGetSymbolAddress((void**)&q, g_q);
  cudaGetSymbolAddress((void**)&k, g_k);
  cudaGetSymbolAddress((void**)&v, g_v);
  cudaGetSymbolAddress((void**)&att, g_att);

  cudaFuncSetAttribute(flash_kernel,
                       cudaFuncAttributeMaxDynamicSharedMemorySize, FLASH_SMEM);

  // 1. QKV projection: [8192,1024] @ [1024,3072]
  dim3 g1(QKVDIM / 64, TOKENS / 64);
  gemm_bias_kernel<<<g1, 256>>>(x, Wqkv, bqkv, qkv, TOKENS, QKVDIM, EMBD);

  // 2. RoPE + split to [B,H,L,Dh]
  rope_split_kernel<<<TOKENS, 256>>>(qkv, q, k, v);

  // 3. Causal flash attention -> [B,L,D]
  dim3 g3(SEQ / 64, NHEAD, BATCH);
  flash_kernel<<<g3, 256, FLASH_SMEM>>>(q, k, v, amask, att);

  // 4. Output projection: [8192,1024] @ [1024,1024]
  dim3 g4(EMBD / 64, TOKENS / 64);
  gemm_bias_kernel<<<g4, 256>>>(att, Wproj, bproj, out, TOKENS, EMBD, EMBD);
}

// round 2
// speedup vs baseline: 2.8474x; 2.8474x over previous
#include <cuda_runtime.h>
#include <math.h>
#include <cstdint>

// Problem constants: B=4, L=2048, D=1024, H=16, Dh=64, 3D=3072
#define BATCH   4
#define SEQ     2048
#define EMBD    1024
#define NHEAD   16
#define HDIM    64
#define TOKENS  (BATCH * SEQ)            // 8192
#define QKVDIM  (3 * EMBD)               // 3072

// ---------------- scratch (static __device__, no allocation) ----------------
__device__ float g_qkv[(size_t)TOKENS * QKVDIM];          // 8192 x 3072
__device__ float g_q[(size_t)BATCH * NHEAD * SEQ * HDIM]; // [B,H,L,Dh]
__device__ float g_k[(size_t)BATCH * NHEAD * SEQ * HDIM];
__device__ float g_v[(size_t)BATCH * NHEAD * SEQ * HDIM];
__device__ float g_att[(size_t)TOKENS * EMBD];            // [B,L,D]

// ---------------- tf32 tensor-core GEMM: C = A @ B + bias ------------------
// 128x128 block tile, BK=32, 256 threads (8 warps, 2x4 warp grid, 64x32/warp),
// cp.async double buffering. A smem stride 36, B smem stride 136 (conflict-free).

__device__ __forceinline__ uint32_t f2tf32(float x) {
  uint32_t u;
  asm("cvt.rna.tf32.f32 %0, %1;" : "=r"(u) : "f"(x));
  return u;
}

__device__ __forceinline__ void mma_tf32(float* d, const uint32_t* a,
                                         const uint32_t* b) {
  asm volatile(
      "mma.sync.aligned.m16n8k8.row.col.f32.tf32.tf32.f32 "
      "{%0,%1,%2,%3},{%4,%5,%6,%7},{%8,%9},{%0,%1,%2,%3};"
      : "+f"(d[0]), "+f"(d[1]), "+f"(d[2]), "+f"(d[3])
      : "r"(a[0]), "r"(a[1]), "r"(a[2]), "r"(a[3]), "r"(b[0]), "r"(b[1]));
}

#define CPA16(dst, src) \
  asm volatile("cp.async.cg.shared.global [%0], [%1], 16;\n" ::"r"(dst), "l"(src))

#define A_STRIDE 36
#define B_STRIDE 136
#define A_BUF_FLOATS (128 * A_STRIDE)   // 4608
#define B_BUF_FLOATS (32 * B_STRIDE)    // 4352
#define GEMM_SMEM ((2 * (A_BUF_FLOATS + B_BUF_FLOATS)) * 4)  // 71680 B

__global__ __launch_bounds__(256) void gemm_tf32_kernel(
    const float* __restrict__ A, const float* __restrict__ B,
    const float* __restrict__ bias, float* __restrict__ C,
    int M, int N, int K) {
  extern __shared__ float sm[];
  const int tid = threadIdx.x;
  const int warp = tid >> 5, lane = tid & 31;
  const int wm = warp >> 2, wn = warp & 3;        // 2 x 4 warp grid
  const int g = lane >> 2, tig = lane & 3;
  const int m0 = blockIdx.y << 7, n0 = blockIdx.x << 7;

  float acc[4][4][4];
#pragma unroll
  for (int i = 0; i < 4; i++)
#pragma unroll
    for (int j = 0; j < 4; j++)
#pragma unroll
      for (int t = 0; t < 4; t++) acc[i][j][t] = 0.0f;

  auto prefetch = [&](int kt, int buf) {
    float* As = sm + buf * A_BUF_FLOATS;
    float* Bs = sm + 2 * A_BUF_FLOATS + buf * B_BUF_FLOATS;
    const int k0 = kt << 5;
#pragma unroll
    for (int j = 0; j < 4; j++) {
      const int p = tid + (j << 8);
      // A: 128 rows x 32 cols = 1024 float4
      const int ar = p >> 3, ac = (p & 7) << 2;
      uint32_t da = (uint32_t)__cvta_generic_to_shared(As + ar * A_STRIDE + ac);
      CPA16(da, A + (size_t)(m0 + ar) * K + k0 + ac);
      // B: 32 rows x 128 cols = 1024 float4
      const int br = p >> 5, bc = (p & 31) << 2;
      uint32_t db = (uint32_t)__cvta_generic_to_shared(Bs + br * B_STRIDE + bc);
      CPA16(db, B + (size_t)(k0 + br) * N + n0 + bc);
    }
    asm volatile("cp.async.commit_group;\n");
  };

  const int NT = K >> 5;
  prefetch(0, 0);

  for (int kt = 0; kt < NT; kt++) {
    const int buf = kt & 1;
    if (kt + 1 < NT) {
      prefetch(kt + 1, buf ^ 1);
      asm volatile("cp.async.wait_group 1;\n");
    } else {
      asm volatile("cp.async.wait_group 0;\n");
    }
    __syncthreads();

    const float* As = sm + buf * A_BUF_FLOATS;
    const float* Bs = sm + 2 * A_BUF_FLOATS + buf * B_BUF_FLOATS;

#pragma unroll
    for (int ks = 0; ks < 4; ks++) {
      const int kk = ks << 3;
      uint32_t af[4][4], bf[4][2];
#pragma unroll
      for (int mt = 0; mt < 4; mt++) {
        const float* ap = As + (wm * 64 + mt * 16 + g) * A_STRIDE + kk + tig;
        af[mt][0] = f2tf32(ap[0]);
        af[mt][2] = f2tf32(ap[4]);
        af[mt][1] = f2tf32(ap[8 * A_STRIDE]);
        af[mt][3] = f2tf32(ap[8 * A_STRIDE + 4]);
      }
#pragma unroll
      for (int nt = 0; nt < 4; nt++) {
        const float* bp = Bs + (kk + tig) * B_STRIDE + wn * 32 + nt * 8 + g;
        bf[nt][0] = f2tf32(bp[0]);
        bf[nt][1] = f2tf32(bp[4 * B_STRIDE]);
      }
#pragma unroll
      for (int mt = 0; mt < 4; mt++)
#pragma unroll
        for (int nt = 0; nt < 4; nt++) mma_tf32(acc[mt][nt], af[mt], bf[nt]);
    }
    __syncthreads();
  }

  // epilogue: add bias, write float2 pairs
#pragma unroll
  for (int mt = 0; mt < 4; mt++) {
    const int r = m0 + wm * 64 + mt * 16 + g;
#pragma unroll
    for (int nt = 0; nt < 4; nt++) {
      const int c = n0 + wn * 32 + nt * 8 + 2 * tig;
      const float b0 = __ldg(bias + c), b1 = __ldg(bias + c + 1);
      float2 v0 = {acc[mt][nt][0] + b0, acc[mt][nt][1] + b1};
      float2 v1 = {acc[mt][nt][2] + b0, acc[mt][nt][3] + b1};
      *(float2*)(C + (size_t)r * N + c) = v0;
      *(float2*)(C + (size_t)(r + 8) * N + c) = v1;
    }
  }
}

// ---------------- RoPE + split/transpose to [B,H,L,Dh] ----------------------
__global__ __launch_bounds__(256) void rope_split_kernel(
    const float* __restrict__ qkv, float* __restrict__ Q,
    float* __restrict__ K, float* __restrict__ V) {
  const int token = blockIdx.x;          // 0..8191
  const int b = token >> 11;             // /2048
  const int l = token & 2047;
  const float* row = qkv + (size_t)token * QKVDIM;
  // q and k: 16 heads * 32 pairs = 512 pairs
  for (int idx = threadIdx.x; idx < 512; idx += 256) {
    const int h = idx >> 5;
    const int i = idx & 31;
    const float inv_freq = 1.0f / powf(10000.0f, (2.0f * (float)i) / 64.0f);
    const float ang = (float)l * inv_freq;
    float s, c;
    sincosf(ang, &s, &c);
    const size_t o = ((size_t)(b * NHEAD + h) * SEQ + l) * HDIM + 2 * i;
    const float q1 = row[h * HDIM + 2 * i];
    const float q2 = row[h * HDIM + 2 * i + 1];
    Q[o]     = q1 * c - q2 * s;
    Q[o + 1] = q1 * s + q2 * c;
    const float k1 = row[EMBD + h * HDIM + 2 * i];
    const float k2 = row[EMBD + h * HDIM + 2 * i + 1];
    K[o]     = k1 * c - k2 * s;
    K[o + 1] = k1 * s + k2 * c;
  }
  // v: plain copy/transpose, 256 float4
  {
    const int idx = threadIdx.x;  // 0..255
    const int h = idx >> 4;
    const int d4 = (idx & 15) << 2;
    float4 vv = *(const float4*)(row + 2 * EMBD + h * HDIM + d4);
    *(float4*)(V + ((size_t)(b * NHEAD + h) * SEQ + l) * HDIM + d4) = vv;
  }
}

// ---------------- causal flash attention (fp32, online softmax) -------------
// Block: one (b, h, 64-row q tile). 256 threads, 4x4 microtiles over 64x64.
#define FLASH_SMEM ((4 * 64 * 65 + 3 * 64) * 4 + 64 * 4)

__global__ __launch_bounds__(256) void flash_kernel(
    const float* __restrict__ Q, const float* __restrict__ K,
    const float* __restrict__ V, const int* __restrict__ amask,
    float* __restrict__ O) {
  extern __shared__ float smf[];
  float* Qs = smf;                // [64][65]
  float* Ks = Qs + 64 * 65;       // [64][65]
  float* Vs = Ks + 64 * 65;       // [64][65]
  float* Ss = Vs + 64 * 65;       // [64][65]
  float* mrow = Ss + 64 * 65;     // [64]
  float* lrow = mrow + 64;        // [64]
  float* crow = lrow + 64;        // [64]
  int*   msk  = (int*)(crow + 64);// [64]

  const int tid = threadIdx.x;
  const int tx = tid & 15, ty = tid >> 4;
  const int qt = blockIdx.x, h = blockIdx.y, b = blockIdx.z;
  const int q0 = qt << 6;
  const size_t base = (size_t)(b * NHEAD + h) * SEQ * HDIM;

  // load Q tile
#pragma unroll
  for (int i = 0; i < 4; i++) {
    const int r = (tid >> 4) + i * 16;
    const int c = (tid & 15) << 2;
    float4 v = *(const float4*)(Q + base + (size_t)(q0 + r) * HDIM + c);
    Qs[r * 65 + c]     = v.x;
    Qs[r * 65 + c + 1] = v.y;
    Qs[r * 65 + c + 2] = v.z;
    Qs[r * 65 + c + 3] = v.w;
  }
  if (tid < 64) { mrow[tid] = -1e30f; lrow[tid] = 0.0f; }
  float acc[4][4] = {};
  __syncthreads();

  for (int kt = 0; kt <= qt; kt++) {
    const int k0 = kt << 6;
    // load K, V tiles + key mask
#pragma unroll
    for (int i = 0; i < 4; i++) {
      const int r = (tid >> 4) + i * 16;
      const int c = (tid & 15) << 2;
      float4 kv = *(const float4*)(K + base + (size_t)(k0 + r) * HDIM + c);
      Ks[r * 65 + c]     = kv.x;
      Ks[r * 65 + c + 1] = kv.y;
      Ks[r * 65 + c + 2] = kv.z;
      Ks[r * 65 + c + 3] = kv.w;
      float4 vv = *(const float4*)(V + base + (size_t)(k0 + r) * HDIM + c);
      Vs[r * 65 + c]     = vv.x;
      Vs[r * 65 + c + 1] = vv.y;
      Vs[r * 65 + c + 2] = vv.z;
      Vs[r * 65 + c + 3] = vv.w;
    }
    if (tid < 64) msk[tid] = amask[b * SEQ + k0 + tid];
    __syncthreads();

    // S = scale * Q K^T with causal + key mask
    {
      float s[4][4] = {};
      for (int d = 0; d < 64; d++) {
        float qr[4], kr[4];
#pragma unroll
        for (int i = 0; i < 4; i++) qr[i] = Qs[((ty << 2) + i) * 65 + d];
#pragma unroll
        for (int j = 0; j < 4; j++) kr[j] = Ks[((tx << 2) + j) * 65 + d];
#pragma unroll
        for (int i = 0; i < 4; i++)
#pragma unroll
          for (int j = 0; j < 4; j++) s[i][j] += qr[i] * kr[j];
      }
      const bool diag = (kt == qt);
#pragma unroll
      for (int i = 0; i < 4; i++) {
        const int r = (ty << 2) + i;
#pragma unroll
        for (int j = 0; j < 4; j++) {
          const int c = (tx << 2) + j;
          const bool ok = (msk[c] != 0) && (!diag || (c <= r));
          Ss[r * 65 + c] = ok ? s[i][j] * 0.125f : -1e30f;
        }
      }
    }
    __syncthreads();

    // online softmax update (4 lanes per row)
    {
      const int r = tid >> 2, p = tid & 3;
      const int cbase = p << 4;
      float mloc = -1e30f;
#pragma unroll
      for (int t = 0; t < 16; t++) mloc = fmaxf(mloc, Ss[r * 65 + cbase + t]);
      mloc = fmaxf(mloc, __shfl_xor_sync(0xffffffffu, mloc, 1));
      mloc = fmaxf(mloc, __shfl_xor_sync(0xffffffffu, mloc, 2));
      const float mold = mrow[r];
      const float mnew = fmaxf(mold, mloc);
      float sloc = 0.0f;
#pragma unroll
      for (int t = 0; t < 16; t++) {
        const float e = __expf(Ss[r * 65 + cbase + t] - mnew);
        Ss[r * 65 + cbase + t] = e;
        sloc += e;
      }
      sloc += __shfl_xor_sync(0xffffffffu, sloc, 1);
      sloc += __shfl_xor_sync(0xffffffffu, sloc, 2);
      if (p == 0) {
        const float corr = __expf(mold - mnew);
        mrow[r] = mnew;
        lrow[r] = lrow[r] * corr + sloc;
        crow[r] = corr;
      }
    }
    __syncthreads();

    // rescale accumulator, then O += P @ V
    {
      float cr[4];
#pragma unroll
      for (int i = 0; i < 4; i++) cr[i] = crow[(ty << 2) + i];
#pragma unroll
      for (int i = 0; i < 4; i++)
#pragma unroll
        for (int j = 0; j < 4; j++) acc[i][j] *= cr[i];
      for (int kk = 0; kk < 64; kk++) {
        float pr[4], vr[4];
#pragma unroll
        for (int i = 0; i < 4; i++) pr[i] = Ss[((ty << 2) + i) * 65 + kk];
#pragma unroll
        for (int j = 0; j < 4; j++) vr[j] = Vs[kk * 65 + (tx << 2) + j];
#pragma unroll
        for (int i = 0; i < 4; i++)
#pragma unroll
          for (int j = 0; j < 4; j++) acc[i][j] += pr[i] * vr[j];
      }
    }
    __syncthreads();
  }

  // write out in [B, L, H*Dh] layout (ready for proj GEMM)
#pragma unroll
  for (int i = 0; i < 4; i++) {
    const int r = (ty << 2) + i;
    const float inv = 1.0f / lrow[r];
    float4 o;
    o.x = acc[i][0] * inv;
    o.y = acc[i][1] * inv;
    o.z = acc[i][2] * inv;
    o.w = acc[i][3] * inv;
    *(float4*)(O + ((size_t)(b * SEQ + q0 + r)) * EMBD + h * HDIM + (tx << 2)) = o;
  }
}

// ---------------------------------------------------------------------------
extern "C" void kernel_launch(void* const* d_in, const int* in_sizes, int n_in,
                              void* d_out, int out_size) {
  const float* x     = (const float*)d_in[0];
  const float* Wqkv  = (const float*)d_in[1];
  const float* bqkv  = (const float*)d_in[2];
  const float* Wproj = (const float*)d_in[3];
  const float* bproj = (const float*)d_in[4];
  const int*   amask = (const int*)d_in[5];
  float* out = (float*)d_out;

  float *qkv, *q, *k, *v, *att;
  cudaGetSymbolAddress((void**)&qkv, g_qkv);
  cudaGetSymbolAddress((void**)&q, g_q);
  cudaGetSymbolAddress((void**)&k, g_k);
  cudaGetSymbolAddress((void**)&v, g_v);
  cudaGetSymbolAddress((void**)&att, g_att);

  cudaFuncSetAttribute(gemm_tf32_kernel,
                       cudaFuncAttributeMaxDynamicSharedMemorySize, GEMM_SMEM);
  cudaFuncSetAttribute(flash_kernel,
                       cudaFuncAttributeMaxDynamicSharedMemorySize, FLASH_SMEM);

  // 1. QKV projection: [8192,1024] @ [1024,3072]
  dim3 g1(QKVDIM / 128, TOKENS / 128);
  gemm_tf32_kernel<<<g1, 256, GEMM_SMEM>>>(x, Wqkv, bqkv, qkv,
                                           TOKENS, QKVDIM, EMBD);

  // 2. RoPE + split to [B,H,L,Dh]
  rope_split_kernel<<<TOKENS, 256>>>(qkv, q, k, v);

  // 3. Causal flash attention -> [B,L,D]
  dim3 g3(SEQ / 64, NHEAD, BATCH);
  flash_kernel<<<g3, 256, FLASH_SMEM>>>(q, k, v, amask, att);

  // 4. Output projection: [8192,1024] @ [1024,1024]
  dim3 g4(EMBD / 128, TOKENS / 128);
  gemm_tf32_kernel<<<g4, 256, GEMM_SMEM>>>(att, Wproj, bproj, out,
                                           TOKENS, EMBD, EMBD);
}

// round 3
// speedup vs baseline: 5.8495x; 2.0543x over previous
#include <cuda_runtime.h>
#include <math.h>
#include <cstdint>

// Problem constants: B=4, L=2048, D=1024, H=16, Dh=64, 3D=3072
#define BATCH   4
#define SEQ     2048
#define EMBD    1024
#define NHEAD   16
#define HDIM    64
#define TOKENS  (BATCH * SEQ)            // 8192
#define QKVDIM  (3 * EMBD)               // 3072

// ---------------- scratch (static __device__, no allocation) ----------------
__device__ float g_qkv[(size_t)TOKENS * QKVDIM];          // 8192 x 3072
__device__ float g_q[(size_t)BATCH * NHEAD * SEQ * HDIM]; // [B,H,L,Dh]
__device__ float g_k[(size_t)BATCH * NHEAD * SEQ * HDIM];
__device__ float g_v[(size_t)BATCH * NHEAD * SEQ * HDIM];
__device__ float g_att[(size_t)TOKENS * EMBD];            // [B,L,D]
__device__ float2 g_rope[(size_t)SEQ * 32];               // cos/sin table

// ---------------- mma helpers ----------------------------------------------
__device__ __forceinline__ uint32_t f2tf32(float x) {
  uint32_t u;
  asm("cvt.rna.tf32.f32 %0, %1;" : "=r"(u) : "f"(x));
  return u;
}
__device__ __forceinline__ float f2tf32f(float x) {
  return __uint_as_float(f2tf32(x));
}

__device__ __forceinline__ void mma_tf32(float* d, const uint32_t* a,
                                         const uint32_t* b) {
  asm volatile(
      "mma.sync.aligned.m16n8k8.row.col.f32.tf32.tf32.f32 "
      "{%0,%1,%2,%3},{%4,%5,%6,%7},{%8,%9},{%0,%1,%2,%3};"
      : "+f"(d[0]), "+f"(d[1]), "+f"(d[2]), "+f"(d[3])
      : "r"(a[0]), "r"(a[1]), "r"(a[2]), "r"(a[3]), "r"(b[0]), "r"(b[1]));
}

#define CPA16(dst, src) \
  asm volatile("cp.async.cg.shared.global [%0], [%1], 16;\n" ::"r"(dst), "l"(src))

// ---------------- tf32 tensor-core GEMM: C = A @ B + bias ------------------
#define A_STRIDE 36
#define B_STRIDE 136
#define A_BUF_FLOATS (128 * A_STRIDE)   // 4608
#define B_BUF_FLOATS (32 * B_STRIDE)    // 4352
#define GEMM_SMEM ((2 * (A_BUF_FLOATS + B_BUF_FLOATS)) * 4)  // 71680 B

__global__ __launch_bounds__(256) void gemm_tf32_kernel(
    const float* __restrict__ A, const float* __restrict__ B,
    const float* __restrict__ bias, float* __restrict__ C,
    int M, int N, int K) {
  extern __shared__ float sm[];
  const int tid = threadIdx.x;
  const int warp = tid >> 5, lane = tid & 31;
  const int wm = warp >> 2, wn = warp & 3;        // 2 x 4 warp grid
  const int g = lane >> 2, tig = lane & 3;
  const int m0 = blockIdx.y << 7, n0 = blockIdx.x << 7;

  float acc[4][4][4];
#pragma unroll
  for (int i = 0; i < 4; i++)
#pragma unroll
    for (int j = 0; j < 4; j++)
#pragma unroll
      for (int t = 0; t < 4; t++) acc[i][j][t] = 0.0f;

  auto prefetch = [&](int kt, int buf) {
    float* As = sm + buf * A_BUF_FLOATS;
    float* Bs = sm + 2 * A_BUF_FLOATS + buf * B_BUF_FLOATS;
    const int k0 = kt << 5;
#pragma unroll
    for (int j = 0; j < 4; j++) {
      const int p = tid + (j << 8);
      const int ar = p >> 3, ac = (p & 7) << 2;
      uint32_t da = (uint32_t)__cvta_generic_to_shared(As + ar * A_STRIDE + ac);
      CPA16(da, A + (size_t)(m0 + ar) * K + k0 + ac);
      const int br = p >> 5, bc = (p & 31) << 2;
      uint32_t db = (uint32_t)__cvta_generic_to_shared(Bs + br * B_STRIDE + bc);
      CPA16(db, B + (size_t)(k0 + br) * N + n0 + bc);
    }
    asm volatile("cp.async.commit_group;\n");
  };

  const int NT = K >> 5;
  prefetch(0, 0);

  for (int kt = 0; kt < NT; kt++) {
    const int buf = kt & 1;
    if (kt + 1 < NT) {
      prefetch(kt + 1, buf ^ 1);
      asm volatile("cp.async.wait_group 1;\n");
    } else {
      asm volatile("cp.async.wait_group 0;\n");
    }
    __syncthreads();

    const float* As = sm + buf * A_BUF_FLOATS;
    const float* Bs = sm + 2 * A_BUF_FLOATS + buf * B_BUF_FLOATS;

#pragma unroll
    for (int ks = 0; ks < 4; ks++) {
      const int kk = ks << 3;
      uint32_t af[4][4], bf[4][2];
#pragma unroll
      for (int mt = 0; mt < 4; mt++) {
        const float* ap = As + (wm * 64 + mt * 16 + g) * A_STRIDE + kk + tig;
        af[mt][0] = f2tf32(ap[0]);
        af[mt][2] = f2tf32(ap[4]);
        af[mt][1] = f2tf32(ap[8 * A_STRIDE]);
        af[mt][3] = f2tf32(ap[8 * A_STRIDE + 4]);
      }
#pragma unroll
      for (int nt = 0; nt < 4; nt++) {
        const float* bp = Bs + (kk + tig) * B_STRIDE + wn * 32 + nt * 8 + g;
        bf[nt][0] = f2tf32(bp[0]);
        bf[nt][1] = f2tf32(bp[4 * B_STRIDE]);
      }
#pragma unroll
      for (int mt = 0; mt < 4; mt++)
#pragma unroll
        for (int nt = 0; nt < 4; nt++) mma_tf32(acc[mt][nt], af[mt], bf[nt]);
    }
    __syncthreads();
  }

#pragma unroll
  for (int mt = 0; mt < 4; mt++) {
    const int r = m0 + wm * 64 + mt * 16 + g;
#pragma unroll
    for (int nt = 0; nt < 4; nt++) {
      const int c = n0 + wn * 32 + nt * 8 + 2 * tig;
      const float b0 = __ldg(bias + c), b1 = __ldg(bias + c + 1);
      float2 v0 = {acc[mt][nt][0] + b0, acc[mt][nt][1] + b1};
      float2 v1 = {acc[mt][nt][2] + b0, acc[mt][nt][3] + b1};
      *(float2*)(C + (size_t)r * N + c) = v0;
      *(float2*)(C + (size_t)(r + 8) * N + c) = v1;
    }
  }
}

// ---------------- RoPE table + split ----------------------------------------
__global__ __launch_bounds__(256) void rope_table_kernel() {
  const int idx = blockIdx.x * 256 + threadIdx.x;  // 0..65535
  const int l = idx >> 5, i = idx & 31;
  const float inv_freq = 1.0f / powf(10000.0f, (2.0f * (float)i) / 64.0f);
  float s, c;
  sincosf((float)l * inv_freq, &s, &c);
  g_rope[idx] = make_float2(c, s);
}

__global__ __launch_bounds__(256) void rope_split_kernel(
    const float* __restrict__ qkv, float* __restrict__ Q,
    float* __restrict__ K, float* __restrict__ V) {
  const int token = blockIdx.x;          // 0..8191
  const int b = token >> 11;             // /2048
  const int l = token & 2047;
  const float* row = qkv + (size_t)token * QKVDIM;
  for (int idx = threadIdx.x; idx < 512; idx += 256) {
    const int h = idx >> 5;
    const int i = idx & 31;
    const float2 cs = g_rope[l * 32 + i];
    const float c = cs.x, s = cs.y;
    const size_t o = ((size_t)(b * NHEAD + h) * SEQ + l) * HDIM + 2 * i;
    const float q1 = row[h * HDIM + 2 * i];
    const float q2 = row[h * HDIM + 2 * i + 1];
    Q[o]     = q1 * c - q2 * s;
    Q[o + 1] = q1 * s + q2 * c;
    const float k1 = row[EMBD + h * HDIM + 2 * i];
    const float k2 = row[EMBD + h * HDIM + 2 * i + 1];
    K[o]     = k1 * c - k2 * s;
    K[o + 1] = k1 * s + k2 * c;
  }
  {
    const int idx = threadIdx.x;  // 0..255
    const int h = idx >> 4;
    const int d4 = (idx & 15) << 2;
    float4 vv = *(const float4*)(row + 2 * EMBD + h * HDIM + d4);
    *(float4*)(V + ((size_t)(b * NHEAD + h) * SEQ + l) * HDIM + d4) = vv;
  }
}

// ---------------- tensor-core causal flash attention ------------------------
// 64 q-rows per block, 4 warps (16 rows each), BN=64 keys per iteration.
// S and P@V via mma.m16n8k8 tf32. Softmax in C-fragment registers.
#define QS_STRIDE 68
#define KS_STRIDE 68
#define VS_STRIDE 72
#define PS_STRIDE 68
#define FLASH_SMEM \
  ((64 * (QS_STRIDE + KS_STRIDE + VS_STRIDE + PS_STRIDE)) * 4 + 64 * 4)

__global__ __launch_bounds__(128) void flash_mma_kernel(
    const float* __restrict__ Q, const float* __restrict__ K,
    const float* __restrict__ V, const int* __restrict__ amask,
    float* __restrict__ O) {
  extern __shared__ float smf[];
  float* Qs = smf;
  float* Ks = Qs + 64 * QS_STRIDE;
  float* Vs = Ks + 64 * KS_STRIDE;
  float* Ps = Vs + 64 * VS_STRIDE;
  int* msk = (int*)(Ps + 64 * PS_STRIDE);

  const int tid = threadIdx.x;
  const int warp = tid >> 5, lane = tid & 31;
  const int g = lane >> 2, tig = lane & 3;
  const int qt = blockIdx.x, h = blockIdx.y, b = blockIdx.z;
  const int q0 = qt << 6;
  const size_t base = (size_t)(b * NHEAD + h) * SEQ * HDIM;

  // load Q tile (pre-scaled by 1/8, tf32-rounded)
#pragma unroll
  for (int i = 0; i < 8; i++) {
    const int p = tid + (i << 7);
    const int r = p >> 4, c = (p & 15) << 2;
    float4 v = *(const float4*)(Q + base + (size_t)(q0 + r) * HDIM + c);
    float* qd = Qs + r * QS_STRIDE + c;
    qd[0] = f2tf32f(v.x * 0.125f);
    qd[1] = f2tf32f(v.y * 0.125f);
    qd[2] = f2tf32f(v.z * 0.125f);
    qd[3] = f2tf32f(v.w * 0.125f);
  }

  float m0 = -1e30f, m1 = -1e30f, l0 = 0.0f, l1 = 0.0f;
  float o[8][4];
#pragma unroll
  for (int nt = 0; nt < 8; nt++)
#pragma unroll
    for (int c = 0; c < 4; c++) o[nt][c] = 0.0f;

  for (int kt = 0; kt <= qt; kt++) {
    const int k0 = kt << 6;
    __syncthreads();  // prior PV reads of Ks/Vs done
#pragma unroll
    for (int i = 0; i < 8; i++) {
      const int p = tid + (i << 7);
      const int r = p >> 4, c = (p & 15) << 2;
      float4 kv = *(const float4*)(K + base + (size_t)(k0 + r) * HDIM + c);
      float* kd = Ks + r * KS_STRIDE + c;
      kd[0] = f2tf32f(kv.x);
      kd[1] = f2tf32f(kv.y);
      kd[2] = f2tf32f(kv.z);
      kd[3] = f2tf32f(kv.w);
      float4 vv = *(const float4*)(V + base + (size_t)(k0 + r) * HDIM + c);
      float* vd = Vs + r * VS_STRIDE + c;
      vd[0] = f2tf32f(vv.x);
      vd[1] = f2tf32f(vv.y);
      vd[2] = f2tf32f(vv.z);
      vd[3] = f2tf32f(vv.w);
    }
    if (tid < 64) msk[tid] = amask[b * SEQ + k0 + tid];
    __syncthreads();

    // ---- S = (Q/8) @ K^T  (16 rows per warp, 64 cols) ----
    float s[8][4];
#pragma unroll
    for (int nt = 0; nt < 8; nt++)
#pragma unroll
      for (int c = 0; c < 4; c++) s[nt][c] = 0.0f;

    const float* qb = Qs + (warp * 16 + g) * QS_STRIDE;
#pragma unroll
    for (int kc = 0; kc < 8; kc++) {
      const int kk = kc << 3;
      uint32_t a[4];
      a[0] = __float_as_uint(qb[kk + tig]);
      a[1] = __float_as_uint(qb[8 * QS_STRIDE + kk + tig]);
      a[2] = __float_as_uint(qb[kk + tig + 4]);
      a[3] = __float_as_uint(qb[8 * QS_STRIDE + kk + tig + 4]);
#pragma unroll
      for (int nt = 0; nt < 8; nt++) {
        const float* kb = Ks + (nt * 8 + g) * KS_STRIDE + kk;
        uint32_t bf[2];
        bf[0] = __float_as_uint(kb[tig]);
        bf[1] = __float_as_uint(kb[tig + 4]);
        mma_tf32(s[nt], a, bf);
      }
    }

    // ---- mask ----
    const bool diag = (kt == qt);
    const int row0 = warp * 16 + g;
#pragma unroll
    for (int nt = 0; nt < 8; nt++) {
      const int c0 = nt * 8 + 2 * tig;
      const int m_a = msk[c0], m_b = msk[c0 + 1];
      if (diag) {
        if (!(m_a && c0 <= row0)) s[nt][0] = -1e30f;
        if (!(m_b && c0 + 1 <= row0)) s[nt][1] = -1e30f;
        if (!(m_a && c0 <= row0 + 8)) s[nt][2] = -1e30f;
        if (!(m_b && c0 + 1 <= row0 + 8)) s[nt][3] = -1e30f;
      } else {
        if (!m_a) { s[nt][0] = -1e30f; s[nt][2] = -1e30f; }
        if (!m_b) { s[nt][1] = -1e30f; s[nt][3] = -1e30f; }
      }
    }

    // ---- online softmax (rows row0 and row0+8) ----
    float mx0 = -1e30f, mx1 = -1e30f;
#pragma unroll
    for (int nt = 0; nt < 8; nt++) {
      mx0 = fmaxf(mx0, fmaxf(s[nt][0], s[nt][1]));
      mx1 = fmaxf(mx1, fmaxf(s[nt][2], s[nt][3]));
    }
    mx0 = fmaxf(mx0, __shfl_xor_sync(0xffffffffu, mx0, 1));
    mx0 = fmaxf(mx0, __shfl_xor_sync(0xffffffffu, mx0, 2));
    mx1 = fmaxf(mx1, __shfl_xor_sync(0xffffffffu, mx1, 1));
    mx1 = fmaxf(mx1, __shfl_xor_sync(0xffffffffu, mx1, 2));
    const float nm0 = fmaxf(m0, mx0), nm1 = fmaxf(m1, mx1);
    const float corr0 = __expf(m0 - nm0), corr1 = __expf(m1 - nm1);
    m0 = nm0;
    m1 = nm1;

    float sum0 = 0.0f, sum1 = 0.0f;
#pragma unroll
    for (int nt = 0; nt < 8; nt++) {
      s[nt][0] = __expf(s[nt][0] - nm0);
      s[nt][1] = __expf(s[nt][1] - nm0);
      s[nt][2] = __expf(s[nt][2] - nm1);
      s[nt][3] = __expf(s[nt][3] - nm1);
      sum0 += s[nt][0] + s[nt][1];
      sum1 += s[nt][2] + s[nt][3];
    }
    sum0 += __shfl_xor_sync(0xffffffffu, sum0, 1);
    sum0 += __shfl_xor_sync(0xffffffffu, sum0, 2);
    sum1 += __shfl_xor_sync(0xffffffffu, sum1, 1);
    sum1 += __shfl_xor_sync(0xffffffffu, sum1, 2);
    l0 = l0 * corr0 + sum0;
    l1 = l1 * corr1 + sum1;

#pragma unroll
    for (int nt = 0; nt < 8; nt++) {
      o[nt][0] *= corr0;
      o[nt][1] *= corr0;
      o[nt][2] *= corr1;
      o[nt][3] *= corr1;
    }

    // ---- stage P into per-warp smem region (C-layout -> A-layout) ----
    float* pr = Ps + (warp * 16 + g) * PS_STRIDE;
#pragma unroll
    for (int nt = 0; nt < 8; nt++) {
      const int c0 = nt * 8 + 2 * tig;
      pr[c0] = f2tf32f(s[nt][0]);
      pr[c0 + 1] = f2tf32f(s[nt][1]);
      pr[8 * PS_STRIDE + c0] = f2tf32f(s[nt][2]);
      pr[8 * PS_STRIDE + c0 + 1] = f2tf32f(s[nt][3]);
    }
    __syncwarp();

    // ---- O += P @ V ----
    const float* pb = Ps + (warp * 16 + g) * PS_STRIDE;
#pragma unroll
    for (int kc = 0; kc < 8; kc++) {
      const int kk = kc << 3;
      uint32_t a[4];
      a[0] = __float_as_uint(pb[kk + tig]);
      a[1] = __float_as_uint(pb[8 * PS_STRIDE + kk + tig]);
      a[2] = __float_as_uint(pb[kk + tig + 4]);
      a[3] = __float_as_uint(pb[8 * PS_STRIDE + kk + tig + 4]);
#pragma unroll
      for (int nt = 0; nt < 8; nt++) {
        const float* vb = Vs + (kk + tig) * VS_STRIDE + nt * 8 + g;
        uint32_t bf[2];
        bf[0] = __float_as_uint(vb[0]);
        bf[1] = __float_as_uint(vb[4 * VS_STRIDE]);
        mma_tf32(o[nt], a, bf);
      }
    }
  }

  // ---- write O / l to [B, L, H*Dh] ----
  const float inv0 = 1.0f / l0, inv1 = 1.0f / l1;
  const int row0 = q0 + warp * 16 + g;
#pragma unroll
  for (int nt = 0; nt < 8; nt++) {
    const int col = h * HDIM + nt * 8 + 2 * tig;
    float2 v0 = {o[nt][0] * inv0, o[nt][1] * inv0};
    float2 v1 = {o[nt][2] * inv1, o[nt][3] * inv1};
    *(float2*)(O + (size_t)(b * SEQ + row0) * EMBD + col) = v0;
    *(float2*)(O + (size_t)(b * SEQ + row0 + 8) * EMBD + col) = v1;
  }
}

// ---------------------------------------------------------------------------
extern "C" void kernel_launch(void* const* d_in, const int* in_sizes, int n_in,
                              void* d_out, int out_size) {
  const float* x     = (const float*)d_in[0];
  const float* Wqkv  = (const float*)d_in[1];
  const float* bqkv  = (const float*)d_in[2];
  const float* Wproj = (const float*)d_in[3];
  const float* bproj = (const float*)d_in[4];
  const int*   amask = (const int*)d_in[5];
  float* out = (float*)d_out;

  float *qkv, *q, *k, *v, *att;
  cudaGetSymbolAddress((void**)&qkv, g_qkv);
  cudaGetSymbolAddress((void**)&q, g_q);
  cudaGetSymbolAddress((void**)&k, g_k);
  cudaGetSymbolAddress((void**)&v, g_v);
  cudaGetSymbolAddress((void**)&att, g_att);

  cudaFuncSetAttribute(gemm_tf32_kernel,
                       cudaFuncAttributeMaxDynamicSharedMemorySize, GEMM_SMEM);
  cudaFuncSetAttribute(flash_mma_kernel,
                       cudaFuncAttributeMaxDynamicSharedMemorySize, FLASH_SMEM);

  // 0. RoPE cos/sin table
  rope_table_kernel<<<SEQ * 32 / 256, 256>>>();

  // 1. QKV projection: [8192,1024] @ [1024,3072]
  dim3 g1(QKVDIM / 128, TOKENS / 128);
  gemm_tf32_kernel<<<g1, 256, GEMM_SMEM>>>(x, Wqkv, bqkv, qkv,
                                           TOKENS, QKVDIM, EMBD);

  // 2. RoPE + split to [B,H,L,Dh]
  rope_split_kernel<<<TOKENS, 256>>>(qkv, q, k, v);

  // 3. Causal flash attention (tensor cores) -> [B,L,D]
  dim3 g3(SEQ / 64, NHEAD, BATCH);
  flash_mma_kernel<<<g3, 128, FLASH_SMEM>>>(q, k, v, amask, att);

  // 4. Output projection: [8192,1024] @ [1024,1024]
  dim3 g4(EMBD / 128, TOKENS / 128);
  gemm_tf32_kernel<<<g4, 256, GEMM_SMEM>>>(att, Wproj, bproj, out,
                                           TOKENS, EMBD, EMBD);
}

// round 4
// speedup vs baseline: 6.5329x; 1.1168x over previous
#include <cuda_runtime.h>
#include <math.h>
#include <cstdint>

// Problem constants: B=4, L=2048, D=1024, H=16, Dh=64, 3D=3072
#define BATCH   4
#define SEQ     2048
#define EMBD    1024
#define NHEAD   16
#define HDIM    64
#define TOKENS  (BATCH * SEQ)            // 8192
#define QKVDIM  (3 * EMBD)               // 3072

// ---------------- scratch (static __device__, no allocation) ----------------
__device__ float g_qkv[(size_t)TOKENS * QKVDIM];          // 8192 x 3072
__device__ float g_q[(size_t)BATCH * NHEAD * SEQ * HDIM]; // [B,H,L,Dh] tf32, /8
__device__ float g_k[(size_t)BATCH * NHEAD * SEQ * HDIM]; // tf32
__device__ float g_v[(size_t)BATCH * NHEAD * SEQ * HDIM]; // tf32
__device__ float g_att[(size_t)TOKENS * EMBD];            // [B,L,D] tf32
__device__ float2 g_rope[(size_t)SEQ * 32];               // cos/sin table
__device__ float g_xc[(size_t)TOKENS * EMBD];             // x rounded to tf32
__device__ float g_wqkv[(size_t)EMBD * QKVDIM];           // W_qkv tf32
__device__ float g_wproj[(size_t)EMBD * EMBD];            // W_proj tf32

// ---------------- helpers ----------------------------------------------
__device__ __forceinline__ uint32_t f2tf32(float x) {
  uint32_t u;
  asm("cvt.rna.tf32.f32 %0, %1;" : "=r"(u) : "f"(x));
  return u;
}
__device__ __forceinline__ float f2tf32f(float x) {
  return __uint_as_float(f2tf32(x));
}

__device__ __forceinline__ void mma_tf32(float* d, const uint32_t* a,
                                         const uint32_t* b) {
  asm volatile(
      "mma.sync.aligned.m16n8k8.row.col.f32.tf32.tf32.f32 "
      "{%0,%1,%2,%3},{%4,%5,%6,%7},{%8,%9},{%0,%1,%2,%3};"
      : "+f"(d[0]), "+f"(d[1]), "+f"(d[2]), "+f"(d[3])
      : "r"(a[0]), "r"(a[1]), "r"(a[2]), "r"(a[3]), "r"(b[0]), "r"(b[1]));
}

#define CPA16(dst, src) \
  asm volatile("cp.async.cg.shared.global [%0], [%1], 16;\n" ::"r"(dst), "l"(src))

// ---------------- tf32 rounding kernel (grid-stride, float4) ----------------
__global__ __launch_bounds__(256) void tf32_round_kernel(
    const float* __restrict__ in, float* __restrict__ out, int n4) {
  int i = blockIdx.x * 256 + threadIdx.x;
  const int stride = gridDim.x * 256;
  for (; i < n4; i += stride) {
    float4 v = ((const float4*)in)[i];
    v.x = f2tf32f(v.x);
    v.y = f2tf32f(v.y);
    v.z = f2tf32f(v.z);
    v.w = f2tf32f(v.w);
    ((float4*)out)[i] = v;
  }
}

// ---------------- tf32 tensor-core GEMM: C = A @ B + bias ------------------
// A and B must already be tf32-rounded fp32.
#define A_STRIDE 36
#define B_STRIDE 136
#define A_BUF_FLOATS (128 * A_STRIDE)   // 4608
#define B_BUF_FLOATS (32 * B_STRIDE)    // 4352
#define GEMM_SMEM ((2 * (A_BUF_FLOATS + B_BUF_FLOATS)) * 4)  // 71680 B

__global__ __launch_bounds__(256) void gemm_tf32_kernel(
    const float* __restrict__ A, const float* __restrict__ B,
    const float* __restrict__ bias, float* __restrict__ C,
    int M, int N, int K) {
  extern __shared__ float sm[];
  const int tid = threadIdx.x;
  const int warp = tid >> 5, lane = tid & 31;
  const int wm = warp >> 2, wn = warp & 3;        // 2 x 4 warp grid
  const int g = lane >> 2, tig = lane & 3;
  const int m0 = blockIdx.y << 7, n0 = blockIdx.x << 7;

  float acc[4][4][4];
#pragma unroll
  for (int i = 0; i < 4; i++)
#pragma unroll
    for (int j = 0; j < 4; j++)
#pragma unroll
      for (int t = 0; t < 4; t++) acc[i][j][t] = 0.0f;

  auto prefetch = [&](int kt, int buf) {
    float* As = sm + buf * A_BUF_FLOATS;
    float* Bs = sm + 2 * A_BUF_FLOATS + buf * B_BUF_FLOATS;
    const int k0 = kt << 5;
#pragma unroll
    for (int j = 0; j < 4; j++) {
      const int p = tid + (j << 8);
      const int ar = p >> 3, ac = (p & 7) << 2;
      uint32_t da = (uint32_t)__cvta_generic_to_shared(As + ar * A_STRIDE + ac);
      CPA16(da, A + (size_t)(m0 + ar) * K + k0 + ac);
      const int br = p >> 5, bc = (p & 31) << 2;
      uint32_t db = (uint32_t)__cvta_generic_to_shared(Bs + br * B_STRIDE + bc);
      CPA16(db, B + (size_t)(k0 + br) * N + n0 + bc);
    }
    asm volatile("cp.async.commit_group;\n");
  };

  const int NT = K >> 5;
  prefetch(0, 0);

  for (int kt = 0; kt < NT; kt++) {
    const int buf = kt & 1;
    if (kt + 1 < NT) {
      prefetch(kt + 1, buf ^ 1);
      asm volatile("cp.async.wait_group 1;\n");
    } else {
      asm volatile("cp.async.wait_group 0;\n");
    }
    __syncthreads();

    const float* As = sm + buf * A_BUF_FLOATS;
    const float* Bs = sm + 2 * A_BUF_FLOATS + buf * B_BUF_FLOATS;

#pragma unroll
    for (int ks = 0; ks < 4; ks++) {
      const int kk = ks << 3;
      uint32_t af[4][4], bf[4][2];
#pragma unroll
      for (int mt = 0; mt < 4; mt++) {
        const float* ap = As + (wm * 64 + mt * 16 + g) * A_STRIDE + kk + tig;
        af[mt][0] = __float_as_uint(ap[0]);
        af[mt][2] = __float_as_uint(ap[4]);
        af[mt][1] = __float_as_uint(ap[8 * A_STRIDE]);
        af[mt][3] = __float_as_uint(ap[8 * A_STRIDE + 4]);
      }
#pragma unroll
      for (int nt = 0; nt < 4; nt++) {
        const float* bp = Bs + (kk + tig) * B_STRIDE + wn * 32 + nt * 8 + g;
        bf[nt][0] = __float_as_uint(bp[0]);
        bf[nt][1] = __float_as_uint(bp[4 * B_STRIDE]);
      }
#pragma unroll
      for (int mt = 0; mt < 4; mt++)
#pragma unroll
        for (int nt = 0; nt < 4; nt++) mma_tf32(acc[mt][nt], af[mt], bf[nt]);
    }
    __syncthreads();
  }

#pragma unroll
  for (int mt = 0; mt < 4; mt++) {
    const int r = m0 + wm * 64 + mt * 16 + g;
#pragma unroll
    for (int nt = 0; nt < 4; nt++) {
      const int c = n0 + wn * 32 + nt * 8 + 2 * tig;
      const float b0 = __ldg(bias + c), b1 = __ldg(bias + c + 1);
      float2 v0 = {acc[mt][nt][0] + b0, acc[mt][nt][1] + b1};
      float2 v1 = {acc[mt][nt][2] + b0, acc[mt][nt][3] + b1};
      *(float2*)(C + (size_t)r * N + c) = v0;
      *(float2*)(C + (size_t)(r + 8) * N + c) = v1;
    }
  }
}

// ---------------- RoPE table + split (emits tf32-rounded Q/8, K, V) ---------
__global__ __launch_bounds__(256) void rope_table_kernel() {
  const int idx = blockIdx.x * 256 + threadIdx.x;  // 0..65535
  const int l = idx >> 5, i = idx & 31;
  const float inv_freq = 1.0f / powf(10000.0f, (2.0f * (float)i) / 64.0f);
  float s, c;
  sincosf((float)l * inv_freq, &s, &c);
  g_rope[idx] = make_float2(c, s);
}

__global__ __launch_bounds__(256) void rope_split_kernel(
    const float* __restrict__ qkv, float* __restrict__ Q,
    float* __restrict__ K, float* __restrict__ V) {
  const int token = blockIdx.x;          // 0..8191
  const int b = token >> 11;             // /2048
  const int l = token & 2047;
  const float* row = qkv + (size_t)token * QKVDIM;
  for (int idx = threadIdx.x; idx < 512; idx += 256) {
    const int h = idx >> 5;
    const int i = idx & 31;
    const float2 cs = g_rope[l * 32 + i];
    const float c = cs.x, s = cs.y;
    const size_t o = ((size_t)(b * NHEAD + h) * SEQ + l) * HDIM + 2 * i;
    const float q1 = row[h * HDIM + 2 * i];
    const float q2 = row[h * HDIM + 2 * i + 1];
    Q[o]     = f2tf32f((q1 * c - q2 * s) * 0.125f);
    Q[o + 1] = f2tf32f((q1 * s + q2 * c) * 0.125f);
    const float k1 = row[EMBD + h * HDIM + 2 * i];
    const float k2 = row[EMBD + h * HDIM + 2 * i + 1];
    K[o]     = f2tf32f(k1 * c - k2 * s);
    K[o + 1] = f2tf32f(k1 * s + k2 * c);
  }
  {
    const int idx = threadIdx.x;  // 0..255
    const int h = idx >> 4;
    const int d4 = (idx & 15) << 2;
    float4 vv = *(const float4*)(row + 2 * EMBD + h * HDIM + d4);
    vv.x = f2tf32f(vv.x);
    vv.y = f2tf32f(vv.y);
    vv.z = f2tf32f(vv.z);
    vv.w = f2tf32f(vv.w);
    *(float4*)(V + ((size_t)(b * NHEAD + h) * SEQ + l) * HDIM + d4) = vv;
  }
}

// ---------------- tensor-core causal flash attention ------------------------
// 64 q-rows per block, 4 warps (16 rows each). Q fragments in registers.
// K/V tiles via cp.async (pre-rounded tf32). P staged via per-warp smem.
#define KS_STRIDE 68
#define VS_STRIDE 72
#define PS_STRIDE 68
#define FLASH_SMEM ((64 * (KS_STRIDE + VS_STRIDE + PS_STRIDE)) * 4 + 64 * 4)

__global__ __launch_bounds__(128, 3) void flash_mma_kernel(
    const float* __restrict__ Q, const float* __restrict__ K,
    const float* __restrict__ V, const int* __restrict__ amask,
    float* __restrict__ O) {
  extern __shared__ float smf[];
  float* Ks = smf;
  float* Vs = Ks + 64 * KS_STRIDE;
  float* Ps = Vs + 64 * VS_STRIDE;
  int* msk = (int*)(Ps + 64 * PS_STRIDE);

  const int tid = threadIdx.x;
  const int warp = tid >> 5, lane = tid & 31;
  const int g = lane >> 2, tig = lane & 3;
  const int qt = blockIdx.x, h = blockIdx.y, b = blockIdx.z;
  const int q0 = qt << 6;
  const size_t base = (size_t)(b * NHEAD + h) * SEQ * HDIM;

  // ---- stage Q tile through Ps smem, then hoist fragments to registers ----
#pragma unroll
  for (int i = 0; i < 8; i++) {
    const int p = tid + (i << 7);
    const int r = p >> 4, c = (p & 15) << 2;
    *(float4*)(Ps + r * PS_STRIDE + c) =
        *(const float4*)(Q + base + (size_t)(q0 + r) * HDIM + c);
  }
  __syncthreads();
  uint32_t qf[8][4];
  {
    const float* qb = Ps + (warp * 16 + g) * PS_STRIDE;
#pragma unroll
    for (int kc = 0; kc < 8; kc++) {
      const int kk = kc << 3;
      qf[kc][0] = __float_as_uint(qb[kk + tig]);
      qf[kc][1] = __float_as_uint(qb[8 * PS_STRIDE + kk + tig]);
      qf[kc][2] = __float_as_uint(qb[kk + tig + 4]);
      qf[kc][3] = __float_as_uint(qb[8 * PS_STRIDE + kk + tig + 4]);
    }
  }
  // per-warp region of Ps is only touched by the owning warp from here on.

  float m0 = -1e30f, m1 = -1e30f, l0 = 0.0f, l1 = 0.0f;
  float o[8][4];
#pragma unroll
  for (int nt = 0; nt < 8; nt++)
#pragma unroll
    for (int c = 0; c < 4; c++) o[nt][c] = 0.0f;

  for (int kt = 0; kt <= qt; kt++) {
    const int k0 = kt << 6;
    __syncthreads();  // prior iteration's Ks/Vs reads complete
    // cp.async fill of K and V tiles (raw 16B copies, already tf32)
#pragma unroll
    for (int i = 0; i < 8; i++) {
      const int p = tid + (i << 7);
      const int r = p >> 4, c = (p & 15) << 2;
      uint32_t dk = (uint32_t)__cvta_generic_to_shared(Ks + r * KS_STRIDE + c);
      CPA16(dk, K + base + (size_t)(k0 + r) * HDIM + c);
      uint32_t dv = (uint32_t)__cvta_generic_to_shared(Vs + r * VS_STRIDE + c);
      CPA16(dv, V + base + (size_t)(k0 + r) * HDIM + c);
    }
    if (tid < 64) msk[tid] = amask[b * SEQ + k0 + tid];
    asm volatile("cp.async.commit_group;\n");
    asm volatile("cp.async.wait_group 0;\n");
    __syncthreads();

    // ---- S = (Q/8) @ K^T ----
    float s[8][4];
#pragma unroll
    for (int nt = 0; nt < 8; nt++)
#pragma unroll
      for (int c = 0; c < 4; c++) s[nt][c] = 0.0f;

#pragma unroll
    for (int kc = 0; kc < 8; kc++) {
      const int kk = kc << 3;
#pragma unroll
      for (int nt = 0; nt < 8; nt++) {
        const float* kb = Ks + (nt * 8 + g) * KS_STRIDE + kk;
        uint32_t bf[2];
        bf[0] = __float_as_uint(kb[tig]);
        bf[1] = __float_as_uint(kb[tig + 4]);
        mma_tf32(s[nt], qf[kc], bf);
      }
    }

    // ---- mask ----
    const bool diag = (kt == qt);
    const int row0 = warp * 16 + g;
#pragma unroll
    for (int nt = 0; nt < 8; nt++) {
      const int c0 = nt * 8 + 2 * tig;
      const int m_a = msk[c0], m_b = msk[c0 + 1];
      if (diag) {
        if (!(m_a && c0 <= row0)) s[nt][0] = -1e30f;
        if (!(m_b && c0 + 1 <= row0)) s[nt][1] = -1e30f;
        if (!(m_a && c0 <= row0 + 8)) s[nt][2] = -1e30f;
        if (!(m_b && c0 + 1 <= row0 + 8)) s[nt][3] = -1e30f;
      } else {
        if (!m_a) { s[nt][0] = -1e30f; s[nt][2] = -1e30f; }
        if (!m_b) { s[nt][1] = -1e30f; s[nt][3] = -1e30f; }
      }
    }

    // ---- online softmax (rows row0 and row0+8) ----
    float mx0 = -1e30f, mx1 = -1e30f;
#pragma unroll
    for (int nt = 0; nt < 8; nt++) {
      mx0 = fmaxf(mx0, fmaxf(s[nt][0], s[nt][1]));
      mx1 = fmaxf(mx1, fmaxf(s[nt][2], s[nt][3]));
    }
    mx0 = fmaxf(mx0, __shfl_xor_sync(0xffffffffu, mx0, 1));
    mx0 = fmaxf(mx0, __shfl_xor_sync(0xffffffffu, mx0, 2));
    mx1 = fmaxf(mx1, __shfl_xor_sync(0xffffffffu, mx1, 1));
    mx1 = fmaxf(mx1, __shfl_xor_sync(0xffffffffu, mx1, 2));
    const float nm0 = fmaxf(m0, mx0), nm1 = fmaxf(m1, mx1);
    const float corr0 = __expf(m0 - nm0), corr1 = __expf(m1 - nm1);
    m0 = nm0;
    m1 = nm1;

    float sum0 = 0.0f, sum1 = 0.0f;
#pragma unroll
    for (int nt = 0; nt < 8; nt++) {
      s[nt][0] = __expf(s[nt][0] - nm0);
      s[nt][1] = __expf(s[nt][1] - nm0);
      s[nt][2] = __expf(s[nt][2] - nm1);
      s[nt][3] = __expf(s[nt][3] - nm1);
      sum0 += s[nt][0] + s[nt][1];
      sum1 += s[nt][2] + s[nt][3];
    }
    sum0 += __shfl_xor_sync(0xffffffffu, sum0, 1);
    sum0 += __shfl_xor_sync(0xffffffffu, sum0, 2);
    sum1 += __shfl_xor_sync(0xffffffffu, sum1, 1);
    sum1 += __shfl_xor_sync(0xffffffffu, sum1, 2);
    l0 = l0 * corr0 + sum0;
    l1 = l1 * corr1 + sum1;

#pragma unroll
    for (int nt = 0; nt < 8; nt++) {
      o[nt][0] *= corr0;
      o[nt][1] *= corr0;
      o[nt][2] *= corr1;
      o[nt][3] *= corr1;
    }

    // ---- stage P into per-warp smem region (C-layout -> A-layout) ----
    float* pr = Ps + (warp * 16 + g) * PS_STRIDE;
#pragma unroll
    for (int nt = 0; nt < 8; nt++) {
      const int c0 = nt * 8 + 2 * tig;
      pr[c0] = f2tf32f(s[nt][0]);
      pr[c0 + 1] = f2tf32f(s[nt][1]);
      pr[8 * PS_STRIDE + c0] = f2tf32f(s[nt][2]);
      pr[8 * PS_STRIDE + c0 + 1] = f2tf32f(s[nt][3]);
    }
    __syncwarp();

    // ---- O += P @ V ----
    const float* pb = Ps + (warp * 16 + g) * PS_STRIDE;
#pragma unroll
    for (int kc = 0; kc < 8; kc++) {
      const int kk = kc << 3;
      uint32_t a[4];
      a[0] = __float_as_uint(pb[kk + tig]);
      a[1] = __float_as_uint(pb[8 * PS_STRIDE + kk + tig]);
      a[2] = __float_as_uint(pb[kk + tig + 4]);
      a[3] = __float_as_uint(pb[8 * PS_STRIDE + kk + tig + 4]);
#pragma unroll
      for (int nt = 0; nt < 8; nt++) {
        const float* vb = Vs + (kk + tig) * VS_STRIDE + nt * 8 + g;
        uint32_t bf[2];
        bf[0] = __float_as_uint(vb[0]);
        bf[1] = __float_as_uint(vb[4 * VS_STRIDE]);
        mma_tf32(o[nt], a, bf);
      }
    }
    __syncwarp();
  }

  // ---- write O / l to [B, L, H*Dh], tf32-rounded for the proj GEMM ----
  const float inv0 = 1.0f / l0, inv1 = 1.0f / l1;
  const int row0 = q0 + warp * 16 + g;
#pragma unroll
  for (int nt = 0; nt < 8; nt++) {
    const int col = h * HDIM + nt * 8 + 2 * tig;
    float2 v0 = {f2tf32f(o[nt][0] * inv0), f2tf32f(o[nt][1] * inv0)};
    float2 v1 = {f2tf32f(o[nt][2] * inv1), f2tf32f(o[nt][3] * inv1)};
    *(float2*)(O + (size_t)(b * SEQ + row0) * EMBD + col) = v0;
    *(float2*)(O + (size_t)(b * SEQ + row0 + 8) * EMBD + col) = v1;
  }
}

// ---------------------------------------------------------------------------
extern "C" void kernel_launch(void* const* d_in, const int* in_sizes, int n_in,
                              void* d_out, int out_size) {
  const float* x     = (const float*)d_in[0];
  const float* Wqkv  = (const float*)d_in[1];
  const float* bqkv  = (const float*)d_in[2];
  const float* Wproj = (const float*)d_in[3];
  const float* bproj = (const float*)d_in[4];
  const int*   amask = (const int*)d_in[5];
  float* out = (float*)d_out;

  float *qkv, *q, *k, *v, *att, *xc, *wqkv, *wproj;
  cudaGetSymbolAddress((void**)&qkv, g_qkv);
  cudaGetSymbolAddress((void**)&q, g_q);
  cudaGetSymbolAddress((void**)&k, g_k);
  cudaGetSymbolAddress((void**)&v, g_v);
  cudaGetSymbolAddress((void**)&att, g_att);
  cudaGetSymbolAddress((void**)&xc, g_xc);
  cudaGetSymbolAddress((void**)&wqkv, g_wqkv);
  cudaGetSymbolAddress((void**)&wproj, g_wproj);

  cudaFuncSetAttribute(gemm_tf32_kernel,
                       cudaFuncAttributeMaxDynamicSharedMemorySize, GEMM_SMEM);
  cudaFuncSetAttribute(flash_mma_kernel,
                       cudaFuncAttributeMaxDynamicSharedMemorySize, FLASH_SMEM);

  // 0. RoPE cos/sin table + tf32 pre-rounding of GEMM operands
  rope_table_kernel<<<SEQ * 32 / 256, 256>>>();
  tf32_round_kernel<<<1184, 256>>>(x, xc, TOKENS * EMBD / 4);
  tf32_round_kernel<<<1184, 256>>>(Wqkv, wqkv, EMBD * QKVDIM / 4);
  tf32_round_kernel<<<1184, 256>>>(Wproj, wproj, EMBD * EMBD / 4);

  // 1. QKV projection: [8192,1024] @ [1024,3072]
  dim3 g1(QKVDIM / 128, TOKENS / 128);
  gemm_tf32_kernel<<<g1, 256, GEMM_SMEM>>>(xc, wqkv, bqkv, qkv,
                                           TOKENS, QKVDIM, EMBD);

  // 2. RoPE + split to [B,H,L,Dh] (tf32-rounded, Q pre-scaled by 1/8)
  rope_split_kernel<<<TOKENS, 256>>>(qkv, q, k, v);

  // 3. Causal flash attention (tensor cores) -> [B,L,D]
  dim3 g3(SEQ / 64, NHEAD, BATCH);
  flash_mma_kernel<<<g3, 128, FLASH_SMEM>>>(q, k, v, amask, att);

  // 4. Output projection: [8192,1024] @ [1024,1024]
  dim3 g4(EMBD / 128, TOKENS / 128);
  gemm_tf32_kernel<<<g4, 256, GEMM_SMEM>>>(att, wproj, bproj, out,
                                           TOKENS, EMBD, EMBD);
}

// round 5
// speedup vs baseline: 6.6713x; 1.0212x over previous
#include <cuda_runtime.h>
#include <math.h>
#include <cstdint>

// Problem constants: B=4, L=2048, D=1024, H=16, Dh=64, 3D=3072
#define BATCH   4
#define SEQ     2048
#define EMBD    1024
#define NHEAD   16
#define HDIM    64
#define TOKENS  (BATCH * SEQ)            // 8192
#define QKVDIM  (3 * EMBD)               // 3072

// ---------------- scratch (static __device__, no allocation) ----------------
__device__ float g_q[(size_t)BATCH * NHEAD * SEQ * HDIM]; // [B,H,L,Dh] tf32, /8
__device__ float g_k[(size_t)BATCH * NHEAD * SEQ * HDIM]; // tf32
__device__ float g_v[(size_t)BATCH * NHEAD * SEQ * HDIM]; // tf32
__device__ float g_att[(size_t)TOKENS * EMBD];            // [B,L,D] tf32
__device__ float2 g_rope[(size_t)SEQ * 32];               // cos/sin table
__device__ float g_xc[(size_t)TOKENS * EMBD];             // x rounded to tf32
__device__ float g_wqkv[(size_t)EMBD * QKVDIM];           // W_qkv tf32
__device__ float g_wproj[(size_t)EMBD * EMBD];            // W_proj tf32

// ---------------- helpers ----------------------------------------------
__device__ __forceinline__ uint32_t f2tf32(float x) {
  uint32_t u;
  asm("cvt.rna.tf32.f32 %0, %1;" : "=r"(u) : "f"(x));
  return u;
}
__device__ __forceinline__ float f2tf32f(float x) {
  return __uint_as_float(f2tf32(x));
}

__device__ __forceinline__ void mma_tf32(float* d, const uint32_t* a,
                                         const uint32_t* b) {
  asm volatile(
      "mma.sync.aligned.m16n8k8.row.col.f32.tf32.tf32.f32 "
      "{%0,%1,%2,%3},{%4,%5,%6,%7},{%8,%9},{%0,%1,%2,%3};"
      : "+f"(d[0]), "+f"(d[1]), "+f"(d[2]), "+f"(d[3])
      : "r"(a[0]), "r"(a[1]), "r"(a[2]), "r"(a[3]), "r"(b[0]), "r"(b[1]));
}

#define CPA16(dst, src) \
  asm volatile("cp.async.cg.shared.global [%0], [%1], 16;\n" ::"r"(dst), "l"(src))

// ---------------- tf32 rounding kernel (grid-stride, float4) ----------------
__global__ __launch_bounds__(256) void tf32_round_kernel(
    const float* __restrict__ in, float* __restrict__ out, int n4) {
  int i = blockIdx.x * 256 + threadIdx.x;
  const int stride = gridDim.x * 256;
  for (; i < n4; i += stride) {
    float4 v = ((const float4*)in)[i];
    v.x = f2tf32f(v.x);
    v.y = f2tf32f(v.y);
    v.z = f2tf32f(v.z);
    v.w = f2tf32f(v.w);
    ((float4*)out)[i] = v;
  }
}

// ---------------- RoPE cos/sin table ----------------------------------------
__global__ __launch_bounds__(256) void rope_table_kernel() {
  const int idx = blockIdx.x * 256 + threadIdx.x;  // 0..65535
  const int l = idx >> 5, i = idx & 31;
  const float inv_freq = 1.0f / powf(10000.0f, (2.0f * (float)i) / 64.0f);
  float s, c;
  sincosf((float)l * inv_freq, &s, &c);
  g_rope[idx] = make_float2(c, s);
}

// ---------------- GEMM core (shared by both GEMM kernels) -------------------
#define A_STRIDE 36
#define B_STRIDE 136
#define A_BUF_FLOATS (128 * A_STRIDE)   // 4608
#define B_BUF_FLOATS (32 * B_STRIDE)    // 4352
#define GEMM_SMEM ((2 * (A_BUF_FLOATS + B_BUF_FLOATS)) * 4)  // 71680 B

// Computes the 128x128 tile accumulators for this thread. acc[mt][nt][4].
__device__ __forceinline__ void gemm_tile_compute(
    const float* __restrict__ A, const float* __restrict__ B, float* sm,
    int m0, int n0, int N, int K, float acc[4][4][4]) {
  const int tid = threadIdx.x;
  const int warp = tid >> 5, lane = tid & 31;
  const int wm = warp >> 2, wn = warp & 3;
  const int g = lane >> 2, tig = lane & 3;

#pragma unroll
  for (int i = 0; i < 4; i++)
#pragma unroll
    for (int j = 0; j < 4; j++)
#pragma unroll
      for (int t = 0; t < 4; t++) acc[i][j][t] = 0.0f;

  auto prefetch = [&](int kt, int buf) {
    float* As = sm + buf * A_BUF_FLOATS;
    float* Bs = sm + 2 * A_BUF_FLOATS + buf * B_BUF_FLOATS;
    const int k0 = kt << 5;
#pragma unroll
    for (int j = 0; j < 4; j++) {
      const int p = tid + (j << 8);
      const int ar = p >> 3, ac = (p & 7) << 2;
      uint32_t da = (uint32_t)__cvta_generic_to_shared(As + ar * A_STRIDE + ac);
      CPA16(da, A + (size_t)(m0 + ar) * K + k0 + ac);
      const int br = p >> 5, bc = (p & 31) << 2;
      uint32_t db = (uint32_t)__cvta_generic_to_shared(Bs + br * B_STRIDE + bc);
      CPA16(db, B + (size_t)(k0 + br) * N + n0 + bc);
    }
    asm volatile("cp.async.commit_group;\n");
  };

  const int NT = K >> 5;
  prefetch(0, 0);

  for (int kt = 0; kt < NT; kt++) {
    const int buf = kt & 1;
    if (kt + 1 < NT) {
      prefetch(kt + 1, buf ^ 1);
      asm volatile("cp.async.wait_group 1;\n");
    } else {
      asm volatile("cp.async.wait_group 0;\n");
    }
    __syncthreads();

    const float* As = sm + buf * A_BUF_FLOATS;
    const float* Bs = sm + 2 * A_BUF_FLOATS + buf * B_BUF_FLOATS;

#pragma unroll
    for (int ks = 0; ks < 4; ks++) {
      const int kk = ks << 3;
      uint32_t af[4][4], bf[4][2];
#pragma unroll
      for (int mt = 0; mt < 4; mt++) {
        const float* ap = As + (wm * 64 + mt * 16 + g) * A_STRIDE + kk + tig;
        af[mt][0] = __float_as_uint(ap[0]);
        af[mt][2] = __float_as_uint(ap[4]);
        af[mt][1] = __float_as_uint(ap[8 * A_STRIDE]);
        af[mt][3] = __float_as_uint(ap[8 * A_STRIDE + 4]);
      }
#pragma unroll
      for (int nt = 0; nt < 4; nt++) {
        const float* bp = Bs + (kk + tig) * B_STRIDE + wn * 32 + nt * 8 + g;
        bf[nt][0] = __float_as_uint(bp[0]);
        bf[nt][1] = __float_as_uint(bp[4 * B_STRIDE]);
      }
#pragma unroll
      for (int mt = 0; mt < 4; mt++)
#pragma unroll
        for (int nt = 0; nt < 4; nt++) mma_tf32(acc[mt][nt], af[mt], bf[nt]);
    }
    __syncthreads();
  }
}

// ---------------- plain GEMM + bias (used for proj) -------------------------
__global__ __launch_bounds__(256) void gemm_tf32_kernel(
    const float* __restrict__ A, const float* __restrict__ B,
    const float* __restrict__ bias, float* __restrict__ C,
    int M, int N, int K) {
  extern __shared__ float sm[];
  const int tid = threadIdx.x;
  const int warp = tid >> 5, lane = tid & 31;
  const int wm = warp >> 2, wn = warp & 3;
  const int g = lane >> 2, tig = lane & 3;
  const int m0 = blockIdx.y << 7, n0 = blockIdx.x << 7;

  float acc[4][4][4];
  gemm_tile_compute(A, B, sm, m0, n0, N, K, acc);

#pragma unroll
  for (int mt = 0; mt < 4; mt++) {
    const int r = m0 + wm * 64 + mt * 16 + g;
#pragma unroll
    for (int nt = 0; nt < 4; nt++) {
      const int c = n0 + wn * 32 + nt * 8 + 2 * tig;
      const float b0 = __ldg(bias + c), b1 = __ldg(bias + c + 1);
      float2 v0 = {acc[mt][nt][0] + b0, acc[mt][nt][1] + b1};
      float2 v1 = {acc[mt][nt][2] + b0, acc[mt][nt][3] + b1};
      *(float2*)(C + (size_t)r * N + c) = v0;
      *(float2*)(C + (size_t)(r + 8) * N + c) = v1;
    }
  }
}

// ---------------- QKV GEMM with fused RoPE/split epilogue -------------------
// Writes directly to g_q (rotated, /8, tf32), g_k (rotated, tf32), g_v (tf32)
// in [B,H,L,Dh] layout. Column block is uniform in {q,k,v} segment.
__global__ __launch_bounds__(256) void gemm_qkv_rope_kernel(
    const float* __restrict__ A, const float* __restrict__ B,
    const float* __restrict__ bias, float* __restrict__ Q,
    float* __restrict__ K, float* __restrict__ V) {
  extern __shared__ float sm[];
  const int tid = threadIdx.x;
  const int warp = tid >> 5, lane = tid & 31;
  const int wm = warp >> 2, wn = warp & 3;
  const int g = lane >> 2, tig = lane & 3;
  const int m0 = blockIdx.y << 7, n0 = blockIdx.x << 7;

  float acc[4][4][4];
  gemm_tile_compute(A, B, sm, m0, n0, QKVDIM, EMBD, acc);

  const int seg = n0 >> 10;  // 0=q, 1=k, 2=v (block-uniform)
  float* dst = (seg == 0) ? Q : (seg == 1) ? K : V;

#pragma unroll
  for (int mt = 0; mt < 4; mt++) {
    const int r = m0 + wm * 64 + mt * 16 + g;  // token row (and r+8)
#pragma unroll
    for (int nt = 0; nt < 4; nt++) {
      const int c = n0 + wn * 32 + nt * 8 + 2 * tig;  // even column
      const float b0 = __ldg(bias + c), b1 = __ldg(bias + c + 1);
      const int d = c & 63;            // dim within head (even)
      const int h = (c & 1023) >> 6;   // head
      const int i = d >> 1;            // rope pair index
      float vals[2][2] = {{acc[mt][nt][0] + b0, acc[mt][nt][1] + b1},
                          {acc[mt][nt][2] + b0, acc[mt][nt][3] + b1}};
#pragma unroll
      for (int rr = 0; rr < 2; rr++) {
        const int m = r + rr * 8;
        const int bb = m >> 11, l = m & 2047;
        float* o = dst + ((size_t)(bb * NHEAD + h) * SEQ + l) * HDIM + d;
        const float x1 = vals[rr][0], x2 = vals[rr][1];
        float2 w;
        if (seg == 0) {
          const float2 cs = g_rope[l * 32 + i];
          w.x = f2tf32f((x1 * cs.x - x2 * cs.y) * 0.125f);
          w.y = f2tf32f((x1 * cs.y + x2 * cs.x) * 0.125f);
        } else if (seg == 1) {
          const float2 cs = g_rope[l * 32 + i];
          w.x = f2tf32f(x1 * cs.x - x2 * cs.y);
          w.y = f2tf32f(x1 * cs.y + x2 * cs.x);
        } else {
          w.x = f2tf32f(x1);
          w.y = f2tf32f(x2);
        }
        *(float2*)o = w;
      }
    }
  }
}

// ---------------- tensor-core causal flash attention ------------------------
// 64 q-rows per block, 4 warps. Q fragments in registers. K/V double-buffered
// via cp.async, prefetching tile kt+1 while computing tile kt.
#define KS_STRIDE 68
#define VS_STRIDE 72
#define PS_STRIDE 68
#define KBUF (64 * KS_STRIDE)
#define VBUF (64 * VS_STRIDE)
#define FLASH_SMEM ((2 * (KBUF + VBUF) + 64 * PS_STRIDE) * 4 + 2 * 64 * 4)

__global__ __launch_bounds__(128, 2) void flash_mma_kernel(
    const float* __restrict__ Q, const float* __restrict__ K,
    const float* __restrict__ V, const int* __restrict__ amask,
    float* __restrict__ O) {
  extern __shared__ float smf[];
  float* Ksb = smf;                    // 2 buffers
  float* Vsb = Ksb + 2 * KBUF;         // 2 buffers
  float* Ps = Vsb + 2 * VBUF;
  int* msk = (int*)(Ps + 64 * PS_STRIDE);  // [2][64]

  const int tid = threadIdx.x;
  const int warp = tid >> 5, lane = tid & 31;
  const int g = lane >> 2, tig = lane & 3;
  const int qt = blockIdx.x, h = blockIdx.y, b = blockIdx.z;
  const int q0 = qt << 6;
  const size_t base = (size_t)(b * NHEAD + h) * SEQ * HDIM;

  // ---- stage Q tile through Ps smem, hoist fragments to registers ----
#pragma unroll
  for (int i = 0; i < 8; i++) {
    const int p = tid + (i << 7);
    const int r = p >> 4, c = (p & 15) << 2;
    *(float4*)(Ps + r * PS_STRIDE + c) =
        *(const float4*)(Q + base + (size_t)(q0 + r) * HDIM + c);
  }
  __syncthreads();
  uint32_t qf[8][4];
  {
    const float* qb = Ps + (warp * 16 + g) * PS_STRIDE;
#pragma unroll
    for (int kc = 0; kc < 8; kc++) {
      const int kk = kc << 3;
      qf[kc][0] = __float_as_uint(qb[kk + tig]);
      qf[kc][1] = __float_as_uint(qb[8 * PS_STRIDE + kk + tig]);
      qf[kc][2] = __float_as_uint(qb[kk + tig + 4]);
      qf[kc][3] = __float_as_uint(qb[8 * PS_STRIDE + kk + tig + 4]);
    }
  }
  __syncthreads();  // Ps now becomes per-warp P staging

  auto prefetch = [&](int kt, int buf) {
    const int k0 = kt << 6;
    float* Ks = Ksb + buf * KBUF;
    float* Vs = Vsb + buf * VBUF;
#pragma unroll
    for (int i = 0; i < 8; i++) {
      const int p = tid + (i << 7);
      const int r = p >> 4, c = (p & 15) << 2;
      uint32_t dk = (uint32_t)__cvta_generic_to_shared(Ks + r * KS_STRIDE + c);
      CPA16(dk, K + base + (size_t)(k0 + r) * HDIM + c);
      uint32_t dv = (uint32_t)__cvta_generic_to_shared(Vs + r * VS_STRIDE + c);
      CPA16(dv, V + base + (size_t)(k0 + r) * HDIM + c);
    }
    if (tid < 64) msk[buf * 64 + tid] = amask[b * SEQ + k0 + tid];
  };

  float m0 = -1e30f, m1 = -1e30f, l0 = 0.0f, l1 = 0.0f;
  float o[8][4];
#pragma unroll
  for (int nt = 0; nt < 8; nt++)
#pragma unroll
    for (int c = 0; c < 4; c++) o[nt][c] = 0.0f;

  prefetch(0, 0);
  asm volatile("cp.async.commit_group;\n");

  for (int kt = 0; kt <= qt; kt++) {
    const int buf = kt & 1;
    // prefetch next tile into the other buffer (its consumers synced last iter)
    if (kt < qt) prefetch(kt + 1, buf ^ 1);
    asm volatile("cp.async.commit_group;\n");
    asm volatile("cp.async.wait_group 1;\n");  // tile kt resident
    __syncthreads();

    const float* Ks = Ksb + buf * KBUF;
    const float* Vs = Vsb + buf * VBUF;
    const int* mk = msk + buf * 64;

    // ---- S = (Q/8) @ K^T ----
    float s[8][4];
#pragma unroll
    for (int nt = 0; nt < 8; nt++)
#pragma unroll
      for (int c = 0; c < 4; c++) s[nt][c] = 0.0f;

#pragma unroll
    for (int kc = 0; kc < 8; kc++) {
      const int kk = kc << 3;
#pragma unroll
      for (int nt = 0; nt < 8; nt++) {
        const float* kb = Ks + (nt * 8 + g) * KS_STRIDE + kk;
        uint32_t bf[2];
        bf[0] = __float_as_uint(kb[tig]);
        bf[1] = __float_as_uint(kb[tig + 4]);
        mma_tf32(s[nt], qf[kc], bf);
      }
    }

    // ---- mask ----
    const bool diag = (kt == qt);
    const int row0 = warp * 16 + g;
#pragma unroll
    for (int nt = 0; nt < 8; nt++) {
      const int c0 = nt * 8 + 2 * tig;
      const int m_a = mk[c0], m_b = mk[c0 + 1];
      if (diag) {
        if (!(m_a && c0 <= row0)) s[nt][0] = -1e30f;
        if (!(m_b && c0 + 1 <= row0)) s[nt][1] = -1e30f;
        if (!(m_a && c0 <= row0 + 8)) s[nt][2] = -1e30f;
        if (!(m_b && c0 + 1 <= row0 + 8)) s[nt][3] = -1e30f;
      } else {
        if (!m_a) { s[nt][0] = -1e30f; s[nt][2] = -1e30f; }
        if (!m_b) { s[nt][1] = -1e30f; s[nt][3] = -1e30f; }
      }
    }

    // ---- online softmax ----
    float mx0 = -1e30f, mx1 = -1e30f;
#pragma unroll
    for (int nt = 0; nt < 8; nt++) {
      mx0 = fmaxf(mx0, fmaxf(s[nt][0], s[nt][1]));
      mx1 = fmaxf(mx1, fmaxf(s[nt][2], s[nt][3]));
    }
    mx0 = fmaxf(mx0, __shfl_xor_sync(0xffffffffu, mx0, 1));
    mx0 = fmaxf(mx0, __shfl_xor_sync(0xffffffffu, mx0, 2));
    mx1 = fmaxf(mx1, __shfl_xor_sync(0xffffffffu, mx1, 1));
    mx1 = fmaxf(mx1, __shfl_xor_sync(0xffffffffu, mx1, 2));
    const float nm0 = fmaxf(m0, mx0), nm1 = fmaxf(m1, mx1);
    const float corr0 = __expf(m0 - nm0), corr1 = __expf(m1 - nm1);
    m0 = nm0;
    m1 = nm1;

    float sum0 = 0.0f, sum1 = 0.0f;
#pragma unroll
    for (int nt = 0; nt < 8; nt++) {
      s[nt][0] = __expf(s[nt][0] - nm0);
      s[nt][1] = __expf(s[nt][1] - nm0);
      s[nt][2] = __expf(s[nt][2] - nm1);
      s[nt][3] = __expf(s[nt][3] - nm1);
      sum0 += s[nt][0] + s[nt][1];
      sum1 += s[nt][2] + s[nt][3];
    }
    sum0 += __shfl_xor_sync(0xffffffffu, sum0, 1);
    sum0 += __shfl_xor_sync(0xffffffffu, sum0, 2);
    sum1 += __shfl_xor_sync(0xffffffffu, sum1, 1);
    sum1 += __shfl_xor_sync(0xffffffffu, sum1, 2);
    l0 = l0 * corr0 + sum0;
    l1 = l1 * corr1 + sum1;

#pragma unroll
    for (int nt = 0; nt < 8; nt++) {
      o[nt][0] *= corr0;
      o[nt][1] *= corr0;
      o[nt][2] *= corr1;
      o[nt][3] *= corr1;
    }

    // ---- stage P (C-layout -> A-layout) in per-warp Ps region ----
    float* pr = Ps + (warp * 16 + g) * PS_STRIDE;
#pragma unroll
    for (int nt = 0; nt < 8; nt++) {
      const int c0 = nt * 8 + 2 * tig;
      pr[c0] = f2tf32f(s[nt][0]);
      pr[c0 + 1] = f2tf32f(s[nt][1]);
      pr[8 * PS_STRIDE + c0] = f2tf32f(s[nt][2]);
      pr[8 * PS_STRIDE + c0 + 1] = f2tf32f(s[nt][3]);
    }
    __syncwarp();

    // ---- O += P @ V ----
    const float* pb = Ps + (warp * 16 + g) * PS_STRIDE;
#pragma unroll
    for (int kc = 0; kc < 8; kc++) {
      const int kk = kc << 3;
      uint32_t a[4];
      a[0] = __float_as_uint(pb[kk + tig]);
      a[1] = __float_as_uint(pb[8 * PS_STRIDE + kk + tig]);
      a[2] = __float_as_uint(pb[kk + tig + 4]);
      a[3] = __float_as_uint(pb[8 * PS_STRIDE + kk + tig + 4]);
#pragma unroll
      for (int nt = 0; nt < 8; nt++) {
        const float* vb = Vs + (kk + tig) * VS_STRIDE + nt * 8 + g;
        uint32_t bf[2];
        bf[0] = __float_as_uint(vb[0]);
        bf[1] = __float_as_uint(vb[4 * VS_STRIDE]);
        mma_tf32(o[nt], a, bf);
      }
    }
    __syncthreads();  // all warps done with Ks/Vs[buf] before it is refilled
  }

  // ---- write O / l to [B, L, H*Dh], tf32-rounded for the proj GEMM ----
  const float inv0 = 1.0f / l0, inv1 = 1.0f / l1;
  const int row0 = q0 + warp * 16 + g;
#pragma unroll
  for (int nt = 0; nt < 8; nt++) {
    const int col = h * HDIM + nt * 8 + 2 * tig;
    float2 v0 = {f2tf32f(o[nt][0] * inv0), f2tf32f(o[nt][1] * inv0)};
    float2 v1 = {f2tf32f(o[nt][2] * inv1), f2tf32f(o[nt][3] * inv1)};
    *(float2*)(O + (size_t)(b * SEQ + row0) * EMBD + col) = v0;
    *(float2*)(O + (size_t)(b * SEQ + row0 + 8) * EMBD + col) = v1;
  }
}

// ---------------------------------------------------------------------------
extern "C" void kernel_launch(void* const* d_in, const int* in_sizes, int n_in,
                              void* d_out, int out_size) {
  const float* x     = (const float*)d_in[0];
  const float* Wqkv  = (const float*)d_in[1];
  const float* bqkv  = (const float*)d_in[2];
  const float* Wproj = (const float*)d_in[3];
  const float* bproj = (const float*)d_in[4];
  const int*   amask = (const int*)d_in[5];
  float* out = (float*)d_out;

  float *q, *k, *v, *att, *xc, *wqkv, *wproj;
  cudaGetSymbolAddress((void**)&q, g_q);
  cudaGetSymbolAddress((void**)&k, g_k);
  cudaGetSymbolAddress((void**)&v, g_v);
  cudaGetSymbolAddress((void**)&att, g_att);
  cudaGetSymbolAddress((void**)&xc, g_xc);
  cudaGetSymbolAddress((void**)&wqkv, g_wqkv);
  cudaGetSymbolAddress((void**)&wproj, g_wproj);

  cudaFuncSetAttribute(gemm_tf32_kernel,
                       cudaFuncAttributeMaxDynamicSharedMemorySize, GEMM_SMEM);
  cudaFuncSetAttribute(gemm_qkv_rope_kernel,
                       cudaFuncAttributeMaxDynamicSharedMemorySize, GEMM_SMEM);
  cudaFuncSetAttribute(flash_mma_kernel,
                       cudaFuncAttributeMaxDynamicSharedMemorySize, FLASH_SMEM);

  // 0. RoPE cos/sin table + tf32 pre-rounding of GEMM operands
  rope_table_kernel<<<SEQ * 32 / 256, 256>>>();
  tf32_round_kernel<<<1184, 256>>>(x, xc, TOKENS * EMBD / 4);
  tf32_round_kernel<<<1184, 256>>>(Wqkv, wqkv, EMBD * QKVDIM / 4);
  tf32_round_kernel<<<1184, 256>>>(Wproj, wproj, EMBD * EMBD / 4);

  // 1. QKV projection + fused RoPE/split -> g_q (/8), g_k, g_v in [B,H,L,Dh]
  dim3 g1(QKVDIM / 128, TOKENS / 128);
  gemm_qkv_rope_kernel<<<g1, 256, GEMM_SMEM>>>(xc, wqkv, bqkv, q, k, v);

  // 2. Causal flash attention (tensor cores, double-buffered) -> [B,L,D]
  dim3 g3(SEQ / 64, NHEAD, BATCH);
  flash_mma_kernel<<<g3, 128, FLASH_SMEM>>>(q, k, v, amask, att);

  // 3. Output projection: [8192,1024] @ [1024,1024]
  dim3 g4(EMBD / 128, TOKENS / 128);
  gemm_tf32_kernel<<<g4, 256, GEMM_SMEM>>>(att, wproj, bproj, out,
                                           TOKENS, EMBD, EMBD);
}